// round 14
// baseline (speedup 1.0000x reference)
#include <cuda_runtime.h>
#include <cuda_bf16.h>
#include <math.h>
#include <stdint.h>

#define S_LEN 2048
#define NHEAD 71
#define HDIM  64
#define H_DIM (NHEAD * HDIM)          /* 4544 */
#define QKV_N ((NHEAD + 2) * HDIM)    /* 4672 */
#define QKV_NP 4736                   /* padded to 128 */
#define HD_NP  4608                   /* padded to 128 */

/* ---- scratch (__device__ globals; no allocs allowed) ---- */
__device__ float g_qkv[(size_t)S_LEN * QKV_N];

__device__ __align__(256) __nv_bfloat16 g_xh[(size_t)S_LEN * H_DIM];
__device__ __align__(256) __nv_bfloat16 g_xl[(size_t)S_LEN * H_DIM];
__device__ __align__(256) __nv_bfloat16 g_wqh[(size_t)H_DIM * QKV_NP];
__device__ __align__(256) __nv_bfloat16 g_wql[(size_t)H_DIM * QKV_NP];
__device__ __align__(256) __nv_bfloat16 g_wdh[(size_t)H_DIM * HD_NP];
__device__ __align__(256) __nv_bfloat16 g_wdl[(size_t)H_DIM * HD_NP];
__device__ __align__(256) __nv_bfloat16 g_ah[(size_t)S_LEN * H_DIM];
__device__ __align__(256) __nv_bfloat16 g_al[(size_t)S_LEN * H_DIM];

__device__ __align__(256) __nv_bfloat16 g_qh2[(size_t)NHEAD * S_LEN * HDIM];
__device__ __align__(256) __nv_bfloat16 g_ql2[(size_t)NHEAD * S_LEN * HDIM];
__device__ __align__(256) __nv_bfloat16 g_khT[(size_t)HDIM * S_LEN];  /* [d][s] */
__device__ __align__(256) __nv_bfloat16 g_klT[(size_t)HDIM * S_LEN];
__device__ __align__(256) __nv_bfloat16 g_vh2[(size_t)S_LEN * HDIM];  /* [s][d] */
__device__ __align__(256) __nv_bfloat16 g_vl2[(size_t)S_LEN * HDIM];

/* =====================================================================
 * fp32 -> (bf16 hi, bf16 lo) split, vectorized by 4.
 * ===================================================================== */
__global__ void split4_kernel(const float* __restrict__ x,
                              __nv_bfloat16* __restrict__ hi,
                              __nv_bfloat16* __restrict__ lo,
                              int n4) {
    int i = blockIdx.x * blockDim.x + threadIdx.x;
    if (i >= n4) return;
    float4 v = ((const float4*)x)[i];
    float vv[4] = {v.x, v.y, v.z, v.w};
    __nv_bfloat16 h[4], l[4];
#pragma unroll
    for (int j = 0; j < 4; j++) {
        h[j] = __float2bfloat16(vv[j]);
        l[j] = __float2bfloat16(vv[j] - __bfloat162float(h[j]));
    }
    ((__nv_bfloat162*)hi)[2 * i + 0] = __nv_bfloat162(h[0], h[1]);
    ((__nv_bfloat162*)hi)[2 * i + 1] = __nv_bfloat162(h[2], h[3]);
    ((__nv_bfloat162*)lo)[2 * i + 0] = __nv_bfloat162(l[0], l[1]);
    ((__nv_bfloat162*)lo)[2 * i + 1] = __nv_bfloat162(l[2], l[3]);
}

/* split weights [K][N] -> [K][Npad] hi/lo, zero-pad n >= N */
__global__ void wsplit_pad_kernel(const float* __restrict__ W,
                                  __nv_bfloat16* __restrict__ Wh,
                                  __nv_bfloat16* __restrict__ Wl,
                                  int N, int Npad, int total) {
    int i = blockIdx.x * blockDim.x + threadIdx.x;
    if (i >= total) return;
    int k = i / Npad;
    int n = i - k * Npad;
    float v = (n < N) ? W[(size_t)k * N + n] : 0.0f;
    __nv_bfloat16 h = __float2bfloat16(v);
    __nv_bfloat16 l = __float2bfloat16(v - __bfloat162float(h));
    Wh[i] = h;
    Wl[i] = l;
}

/* ---- mma / async helpers ---- */
__device__ __forceinline__ void ldm_x4(uint32_t* r, uint32_t addr) {
    asm volatile("ldmatrix.sync.aligned.m8n8.x4.shared.b16 {%0,%1,%2,%3}, [%4];\n"
                 : "=r"(r[0]), "=r"(r[1]), "=r"(r[2]), "=r"(r[3]) : "r"(addr));
}
__device__ __forceinline__ void ldm_x4_t(uint32_t* r, uint32_t addr) {
    asm volatile("ldmatrix.sync.aligned.m8n8.x4.trans.shared.b16 {%0,%1,%2,%3}, [%4];\n"
                 : "=r"(r[0]), "=r"(r[1]), "=r"(r[2]), "=r"(r[3]) : "r"(addr));
}
__device__ __forceinline__ void mma_bf16(float* c, const uint32_t* a, const uint32_t* b) {
    asm volatile(
        "mma.sync.aligned.m16n8k16.row.col.f32.bf16.bf16.f32 "
        "{%0,%1,%2,%3}, {%4,%5,%6,%7}, {%8,%9}, {%0,%1,%2,%3};\n"
        : "+f"(c[0]), "+f"(c[1]), "+f"(c[2]), "+f"(c[3])
        : "r"(a[0]), "r"(a[1]), "r"(a[2]), "r"(a[3]), "r"(b[0]), "r"(b[1]));
}
__device__ __forceinline__ void cp16(uint32_t saddr, const void* gaddr) {
    asm volatile("cp.async.cg.shared.global [%0], [%1], 16;\n"
                 :: "r"(saddr), "l"(gaddr));
}
__device__ __forceinline__ void cp_commit() { asm volatile("cp.async.commit_group;\n"); }
template<int N> __device__ __forceinline__ void cp_wait() {
    asm volatile("cp.async.wait_group %0;\n" :: "n"(N));
}

/* FMA-only exp2 (no MUFU). abs err < 2e-5. */
__device__ __forceinline__ float exp2_fast(float x) {
    x = fmaxf(x, -120.0f);
    float fl = floorf(x);
    float f = x - fl;
    float p = fmaf(f, 1.540353e-4f, 1.3333558e-3f);
    p = fmaf(f, p, 9.6181291e-3f);
    p = fmaf(f, p, 5.5504109e-2f);
    p = fmaf(f, p, 2.4022651e-1f);
    p = fmaf(f, p, 6.9314718e-1f);
    p = fmaf(f, p, 1.0f);
    return __int_as_float(((int)fl + 127) << 23) * p;
}

/* =====================================================================
 * Split-bf16 GEMM v4 (unchanged from R12 WIN).
 * ===================================================================== */
#define APITCH 40
#define BPITCH 136
#define A_TILE (128 * APITCH)
#define B_TILE (32 * BPITCH)
#define OFF_AH 0
#define OFF_AL (A_TILE)
#define OFF_BH (2 * A_TILE)
#define OFF_BL (2 * A_TILE + B_TILE)
#define STAGE_ELEMS (2 * A_TILE + 2 * B_TILE)
#define GEMM_SMEM_BYTES (2 * STAGE_ELEMS * 2)

__global__ void __launch_bounds__(128, 2)
gemm_bf16split_v4(const __nv_bfloat16* __restrict__ Ah,
                  const __nv_bfloat16* __restrict__ Al,
                  const __nv_bfloat16* __restrict__ Bh,
                  const __nv_bfloat16* __restrict__ Bl,
                  float* __restrict__ C,
                  int M, int N, int Npad, int K) {
    extern __shared__ __nv_bfloat16 sm[];
    uint32_t sbase = (uint32_t)__cvta_generic_to_shared(sm);

    const int tid  = threadIdx.x;
    const int lane = tid & 31;
    const int wid  = tid >> 5;
    const int wm   = (wid & 1) * 64;
    const int wn   = (wid >> 1) * 64;
    const int rowBlk = blockIdx.y * 128;
    const int colBlk = blockIdx.x * 128;

    const int arA = tid >> 2;
    const int acA = (tid & 3) * 8;
    const int brB = tid >> 4;
    const int bcB = (tid & 15) * 8;

    const __nv_bfloat16* pAh = Ah + (size_t)(rowBlk + arA) * K + acA;
    const __nv_bfloat16* pAl = Al + (size_t)(rowBlk + arA) * K + acA;
    const __nv_bfloat16* pBh = Bh + (size_t)brB * Npad + colBlk + bcB;
    const __nv_bfloat16* pBl = Bl + (size_t)brB * Npad + colBlk + bcB;

    const uint32_t sAh = sbase + (uint32_t)(OFF_AH + arA * APITCH + acA) * 2;
    const uint32_t sAl = sbase + (uint32_t)(OFF_AL + arA * APITCH + acA) * 2;
    const uint32_t sBh = sbase + (uint32_t)(OFF_BH + brB * BPITCH + bcB) * 2;
    const uint32_t sBl = sbase + (uint32_t)(OFF_BL + brB * BPITCH + bcB) * 2;

    const int lr = lane & 15;
    const int lc = (lane >> 4) << 3;

    float acc[4][8][4];
#pragma unroll
    for (int mt = 0; mt < 4; mt++)
#pragma unroll
        for (int nt = 0; nt < 8; nt++)
#pragma unroll
            for (int r = 0; r < 4; r++) acc[mt][nt][r] = 0.0f;

    const int iters = K / 32;

    auto issue = [&](int it, int s) {
        uint32_t so = (uint32_t)(s * STAGE_ELEMS) * 2;
        int ko = it * 32;
#pragma unroll
        for (int i = 0; i < 4; i++) {
            cp16(sAh + so + (uint32_t)(i * 32 * APITCH) * 2, pAh + (size_t)i * 32 * K + ko);
            cp16(sAl + so + (uint32_t)(i * 32 * APITCH) * 2, pAl + (size_t)i * 32 * K + ko);
        }
#pragma unroll
        for (int i = 0; i < 4; i++) {
            cp16(sBh + so + (uint32_t)(i * 8 * BPITCH) * 2, pBh + (size_t)(i * 8 + ko) * Npad);
            cp16(sBl + so + (uint32_t)(i * 8 * BPITCH) * 2, pBl + (size_t)(i * 8 + ko) * Npad);
        }
        cp_commit();
    };

    issue(0, 0);

    for (int it = 0; it < iters; it++) {
        int s = it & 1;
        if (it + 1 < iters) {
            issue(it + 1, s ^ 1);
            cp_wait<1>();
        } else {
            cp_wait<0>();
        }
        __syncthreads();

        uint32_t sb = sbase + (uint32_t)(s * STAGE_ELEMS) * 2;
#pragma unroll
        for (int kk = 0; kk < 32; kk += 16) {
            uint32_t ah[4][4], al[4][4];
#pragma unroll
            for (int mt = 0; mt < 4; mt++) {
                uint32_t arow = (uint32_t)(wm + mt * 16 + lr);
                uint32_t acol = (uint32_t)(kk + lc);
                ldm_x4(ah[mt], sb + (uint32_t)(OFF_AH) * 2 + (arow * APITCH + acol) * 2);
                ldm_x4(al[mt], sb + (uint32_t)(OFF_AL) * 2 + (arow * APITCH + acol) * 2);
            }
#pragma unroll
            for (int nh = 0; nh < 4; nh++) {
                uint32_t bh[4], bl[4];
                uint32_t brow = (uint32_t)(kk + lr);
                uint32_t bcol = (uint32_t)(wn + nh * 16 + lc);
                ldm_x4_t(bh, sb + (uint32_t)(OFF_BH) * 2 + (brow * BPITCH + bcol) * 2);
                ldm_x4_t(bl, sb + (uint32_t)(OFF_BL) * 2 + (brow * BPITCH + bcol) * 2);
#pragma unroll
                for (int mt = 0; mt < 4; mt++) {
                    mma_bf16(acc[mt][2 * nh + 0], ah[mt], &bh[0]);
                    mma_bf16(acc[mt][2 * nh + 0], ah[mt], &bl[0]);
                    mma_bf16(acc[mt][2 * nh + 0], al[mt], &bh[0]);
                    mma_bf16(acc[mt][2 * nh + 1], ah[mt], &bh[2]);
                    mma_bf16(acc[mt][2 * nh + 1], ah[mt], &bl[2]);
                    mma_bf16(acc[mt][2 * nh + 1], al[mt], &bh[2]);
                }
            }
        }
        __syncthreads();
    }

#pragma unroll
    for (int mt = 0; mt < 4; mt++) {
        int row = rowBlk + wm + mt * 16 + (lane >> 2);
#pragma unroll
        for (int nt = 0; nt < 8; nt++) {
            int col = colBlk + wn + nt * 8 + (lane & 3) * 2;
            if (col < N) {
                *(float2*)&C[(size_t)row * N + col] =
                    make_float2(acc[mt][nt][0], acc[mt][nt][1]);
                *(float2*)&C[(size_t)(row + 8) * N + col] =
                    make_float2(acc[mt][nt][2], acc[mt][nt][3]);
            }
        }
    }
}

/* =====================================================================
 * RoPE + split to bf16 hi/lo (unchanged).
 * ===================================================================== */
__global__ void rope_split_bf16_kernel(const float* __restrict__ qkv,
                                       __nv_bfloat16* __restrict__ qh,
                                       __nv_bfloat16* __restrict__ ql,
                                       __nv_bfloat16* __restrict__ khT,
                                       __nv_bfloat16* __restrict__ klT,
                                       __nv_bfloat16* __restrict__ vh,
                                       __nv_bfloat16* __restrict__ vl) {
    __shared__ float cs_s[32], sn_s[32];
    const int s = blockIdx.x;
    const float* row = qkv + (size_t)s * QKV_N;

    if (threadIdx.x < 32) {
        const float L2C = 13.28771237954945f / 32.0f;
        float inv = exp2f(-(float)threadIdx.x * L2C);
        float sn, cs;
        sincosf((float)s * inv, &sn, &cs);
        cs_s[threadIdx.x] = cs;
        sn_s[threadIdx.x] = sn;
    }
    __syncthreads();

    for (int col = threadIdx.x; col < QKV_N; col += blockDim.x) {
        const int h = col >> 6;
        const int d = col & 63;
        float val = row[col];
        float o;
        if (h < NHEAD + 1) {
            const int jj = d & 31;
            float other = (d < 32) ? -row[h * 64 + d + 32] : row[h * 64 + d - 32];
            o = val * cs_s[jj] + other * sn_s[jj];
        } else {
            o = val;
        }
        __nv_bfloat16 hi = __float2bfloat16(o);
        __nv_bfloat16 lo = __float2bfloat16(o - __bfloat162float(hi));
        if (h < NHEAD) {
            size_t idx = ((size_t)h * S_LEN + s) * HDIM + d;
            qh[idx] = hi; ql[idx] = lo;
        } else if (h == NHEAD) {
            size_t idx = (size_t)d * S_LEN + s;
            khT[idx] = hi; klT[idx] = lo;
        } else {
            size_t idx = (size_t)s * HDIM + d;
            vh[idx] = hi; vl[idx] = lo;
        }
    }
}

/* =====================================================================
 * Tensor-core flash attention v2: 128-row Q tile, 8 warps, 256 thr.
 * Warp w owns q rows [16w, 16w+16). KV tiles of 64; jt = 0..2qt+1.
 * Longest blocks launched first (qt reversed on host side).
 * ===================================================================== */
#define AT_PITCH 72
#define ROW_QH 0
#define ROW_QL 128
#define ROW_KH 256
#define ROW_KL 320
#define ROW_VH 384
#define ROW_VL 448
#define AT2_SMEM_BYTES (512 * AT_PITCH * 2)   /* 73728 */

__global__ void __launch_bounds__(256, 2)
attn_mma_kernel(const __nv_bfloat16* __restrict__ Qh,
                const __nv_bfloat16* __restrict__ Ql,
                const __nv_bfloat16* __restrict__ KhT,
                const __nv_bfloat16* __restrict__ KlT,
                const __nv_bfloat16* __restrict__ Vh,
                const __nv_bfloat16* __restrict__ Vl,
                __nv_bfloat16* __restrict__ Oh,
                __nv_bfloat16* __restrict__ Ol) {
    extern __shared__ unsigned char sraw[];
    __nv_bfloat16* S = (__nv_bfloat16*)sraw;
    uint32_t sbase = (uint32_t)__cvta_generic_to_shared(S);

    const int tid  = threadIdx.x;
    const int lane = tid & 31;
    const int w    = tid >> 5;                 /* 0..7 */
    const int qt   = gridDim.x - 1 - blockIdx.x;  /* long blocks first */
    const int h    = blockIdx.y;
    const int qs0  = qt * 128;

    const int lr = lane & 15;
    const int lc = (lane >> 4) << 3;
    const int qr = lane >> 2;
    const int qc = (lane & 3) * 2;

    /* load Q hi/lo tiles (128x64 each) */
    {
        const __nv_bfloat16* qhg = Qh + ((size_t)h * S_LEN + qs0) * HDIM;
        const __nv_bfloat16* qlg = Ql + ((size_t)h * S_LEN + qs0) * HDIM;
        for (int i = tid; i < 1024; i += 256) {
            int r = i >> 3, c = (i & 7) * 8;
            *(uint4*)&S[(ROW_QH + r) * AT_PITCH + c] = *(const uint4*)&qhg[r * 64 + c];
            *(uint4*)&S[(ROW_QL + r) * AT_PITCH + c] = *(const uint4*)&qlg[r * 64 + c];
        }
    }

    float m1 = -1e30f, m2 = -1e30f, l1 = 0.0f, l2 = 0.0f;
    float o[8][4];
#pragma unroll
    for (int nt = 0; nt < 8; nt++)
#pragma unroll
        for (int j = 0; j < 4; j++) o[nt][j] = 0.0f;

    const float SC = 0.125f * 1.4426950408889634f;
    const int row1 = w * 16 + qr;
    const int row2 = row1 + 8;
    const int grow1 = qs0 + row1;
    const int grow2 = qs0 + row2;
    const int jtmax = 2 * qt + 1;

    for (int jt = 0; jt <= jtmax; jt++) {
        for (int i = tid; i < 512; i += 256) {
            int r = i >> 3, c = (i & 7) * 8;
            *(uint4*)&S[(ROW_KH + r) * AT_PITCH + c] =
                *(const uint4*)&KhT[(size_t)r * S_LEN + jt * 64 + c];
            *(uint4*)&S[(ROW_KL + r) * AT_PITCH + c] =
                *(const uint4*)&KlT[(size_t)r * S_LEN + jt * 64 + c];
            *(uint4*)&S[(ROW_VH + r) * AT_PITCH + c] =
                *(const uint4*)&Vh[(size_t)(jt * 64 + r) * 64 + c];
            *(uint4*)&S[(ROW_VL + r) * AT_PITCH + c] =
                *(const uint4*)&Vl[(size_t)(jt * 64 + r) * 64 + c];
        }
        __syncthreads();

        float s[8][4];
#pragma unroll
        for (int nt = 0; nt < 8; nt++)
#pragma unroll
            for (int j = 0; j < 4; j++) s[nt][j] = 0.0f;

#pragma unroll
        for (int kk = 0; kk < 64; kk += 16) {
            uint32_t qfh[4], qfl[4];
            ldm_x4(qfh, sbase + (uint32_t)((ROW_QH + w * 16 + lr) * AT_PITCH + kk + lc) * 2);
            ldm_x4(qfl, sbase + (uint32_t)((ROW_QL + w * 16 + lr) * AT_PITCH + kk + lc) * 2);
#pragma unroll
            for (int half = 0; half < 4; half++) {
                uint32_t bh[2][2], bl[2][2], r4[4];
                ldm_x4_t(r4, sbase + (uint32_t)((ROW_KH + kk + lr) * AT_PITCH + half * 16 + lc) * 2);
                bh[0][0] = r4[0]; bh[0][1] = r4[1]; bh[1][0] = r4[2]; bh[1][1] = r4[3];
                ldm_x4_t(r4, sbase + (uint32_t)((ROW_KL + kk + lr) * AT_PITCH + half * 16 + lc) * 2);
                bl[0][0] = r4[0]; bl[0][1] = r4[1]; bl[1][0] = r4[2]; bl[1][1] = r4[3];
#pragma unroll
                for (int t = 0; t < 2; t++) {
                    int nt = half * 2 + t;
                    mma_bf16(s[nt], qfh, bh[t]);
                    mma_bf16(s[nt], qfh, bl[t]);
                    mma_bf16(s[nt], qfl, bh[t]);
                }
            }
        }

#pragma unroll
        for (int nt = 0; nt < 8; nt++)
#pragma unroll
            for (int j = 0; j < 4; j++) s[nt][j] *= SC;

        if (jt >= 2 * qt) {
            int cbase = jt * 64;
#pragma unroll
            for (int nt = 0; nt < 8; nt++) {
                int c0 = cbase + nt * 8 + qc;
                if (c0     > grow1) s[nt][0] = -1e30f;
                if (c0 + 1 > grow1) s[nt][1] = -1e30f;
                if (c0     > grow2) s[nt][2] = -1e30f;
                if (c0 + 1 > grow2) s[nt][3] = -1e30f;
            }
        }

        float pm1 = -1e30f, pm2 = -1e30f;
#pragma unroll
        for (int nt = 0; nt < 8; nt++) {
            pm1 = fmaxf(pm1, fmaxf(s[nt][0], s[nt][1]));
            pm2 = fmaxf(pm2, fmaxf(s[nt][2], s[nt][3]));
        }
        pm1 = fmaxf(pm1, __shfl_xor_sync(0xffffffff, pm1, 1));
        pm1 = fmaxf(pm1, __shfl_xor_sync(0xffffffff, pm1, 2));
        pm2 = fmaxf(pm2, __shfl_xor_sync(0xffffffff, pm2, 1));
        pm2 = fmaxf(pm2, __shfl_xor_sync(0xffffffff, pm2, 2));

        float mn1 = fmaxf(m1, pm1), mn2 = fmaxf(m2, pm2);
        float rs1 = exp2_fast(m1 - mn1), rs2 = exp2_fast(m2 - mn2);
        m1 = mn1; m2 = mn2;

        float sum1 = 0.0f, sum2 = 0.0f;
        uint32_t phA[8], phB[8], plA[8], plB[8];
#pragma unroll
        for (int nt = 0; nt < 8; nt++) {
            float e0 = exp2_fast(s[nt][0] - m1);
            float e1 = exp2_fast(s[nt][1] - m1);
            float e2 = exp2_fast(s[nt][2] - m2);
            float e3 = exp2_fast(s[nt][3] - m2);
            sum1 += e0 + e1;
            sum2 += e2 + e3;
            __nv_bfloat162 h01 = __floats2bfloat162_rn(e0, e1);
            __nv_bfloat162 h23 = __floats2bfloat162_rn(e2, e3);
            float r0 = e0 - __bfloat162float(h01.x);
            float r1 = e1 - __bfloat162float(h01.y);
            float r2 = e2 - __bfloat162float(h23.x);
            float r3 = e3 - __bfloat162float(h23.y);
            __nv_bfloat162 l01 = __floats2bfloat162_rn(r0, r1);
            __nv_bfloat162 l23 = __floats2bfloat162_rn(r2, r3);
            phA[nt] = *(uint32_t*)&h01;  phB[nt] = *(uint32_t*)&h23;
            plA[nt] = *(uint32_t*)&l01;  plB[nt] = *(uint32_t*)&l23;
        }
        sum1 += __shfl_xor_sync(0xffffffff, sum1, 1);
        sum1 += __shfl_xor_sync(0xffffffff, sum1, 2);
        sum2 += __shfl_xor_sync(0xffffffff, sum2, 1);
        sum2 += __shfl_xor_sync(0xffffffff, sum2, 2);
        l1 = l1 * rs1 + sum1;
        l2 = l2 * rs2 + sum2;

#pragma unroll
        for (int nt = 0; nt < 8; nt++) {
            o[nt][0] *= rs1; o[nt][1] *= rs1;
            o[nt][2] *= rs2; o[nt][3] *= rs2;
        }

#pragma unroll
        for (int t = 0; t < 4; t++) {
            uint32_t aH[4] = {phA[2 * t], phB[2 * t], phA[2 * t + 1], phB[2 * t + 1]};
            uint32_t aL[4] = {plA[2 * t], plB[2 * t], plA[2 * t + 1], plB[2 * t + 1]};
#pragma unroll
            for (int half = 0; half < 4; half++) {
                uint32_t bh[2][2], bl[2][2], r4[4];
                ldm_x4_t(r4, sbase + (uint32_t)((ROW_VH + t * 16 + lr) * AT_PITCH + half * 16 + lc) * 2);
                bh[0][0] = r4[0]; bh[0][1] = r4[1]; bh[1][0] = r4[2]; bh[1][1] = r4[3];
                ldm_x4_t(r4, sbase + (uint32_t)((ROW_VL + t * 16 + lr) * AT_PITCH + half * 16 + lc) * 2);
                bl[0][0] = r4[0]; bl[0][1] = r4[1]; bl[1][0] = r4[2]; bl[1][1] = r4[3];
#pragma unroll
                for (int tt = 0; tt < 2; tt++) {
                    int nt = half * 2 + tt;
                    mma_bf16(o[nt], aH, bh[tt]);
                    mma_bf16(o[nt], aL, bh[tt]);
                    mma_bf16(o[nt], aH, bl[tt]);
                }
            }
        }
        __syncthreads();
    }

    float inv1 = 1.0f / l1, inv2 = 1.0f / l2;
#pragma unroll
    for (int nt = 0; nt < 8; nt++) {
        int col = h * 64 + nt * 8 + qc;
        float v0 = o[nt][0] * inv1, v1 = o[nt][1] * inv1;
        float v2 = o[nt][2] * inv2, v3 = o[nt][3] * inv2;
        __nv_bfloat162 h01 = __floats2bfloat162_rn(v0, v1);
        __nv_bfloat162 h23 = __floats2bfloat162_rn(v2, v3);
        __nv_bfloat162 l01 = __floats2bfloat162_rn(v0 - __bfloat162float(h01.x),
                                                   v1 - __bfloat162float(h01.y));
        __nv_bfloat162 l23 = __floats2bfloat162_rn(v2 - __bfloat162float(h23.x),
                                                   v3 - __bfloat162float(h23.y));
        *(uint32_t*)&Oh[(size_t)grow1 * H_DIM + col] = *(uint32_t*)&h01;
        *(uint32_t*)&Ol[(size_t)grow1 * H_DIM + col] = *(uint32_t*)&l01;
        *(uint32_t*)&Oh[(size_t)grow2 * H_DIM + col] = *(uint32_t*)&h23;
        *(uint32_t*)&Ol[(size_t)grow2 * H_DIM + col] = *(uint32_t*)&l23;
    }
}

/* ===================================================================== */
extern "C" void kernel_launch(void* const* d_in, const int* in_sizes, int n_in,
                              void* d_out, int out_size) {
    const float* hidden  = (const float*)d_in[0];
    const float* qkv_w   = (const float*)d_in[2];
    const float* dense_w = (const float*)d_in[3];
    float* out = (float*)d_out;

    float* qkv_p;
    cudaGetSymbolAddress((void**)&qkv_p, g_qkv);

    __nv_bfloat16 *xh, *xl, *wqh, *wql, *wdh, *wdl, *ah, *al;
    __nv_bfloat16 *qh2, *ql2, *khT, *klT, *vh2, *vl2;
    cudaGetSymbolAddress((void**)&xh,  g_xh);
    cudaGetSymbolAddress((void**)&xl,  g_xl);
    cudaGetSymbolAddress((void**)&wqh, g_wqh);
    cudaGetSymbolAddress((void**)&wql, g_wql);
    cudaGetSymbolAddress((void**)&wdh, g_wdh);
    cudaGetSymbolAddress((void**)&wdl, g_wdl);
    cudaGetSymbolAddress((void**)&ah,  g_ah);
    cudaGetSymbolAddress((void**)&al,  g_al);
    cudaGetSymbolAddress((void**)&qh2, g_qh2);
    cudaGetSymbolAddress((void**)&ql2, g_ql2);
    cudaGetSymbolAddress((void**)&khT, g_khT);
    cudaGetSymbolAddress((void**)&klT, g_klT);
    cudaGetSymbolAddress((void**)&vh2, g_vh2);
    cudaGetSymbolAddress((void**)&vl2, g_vl2);

    cudaFuncSetAttribute(attn_mma_kernel, cudaFuncAttributeMaxDynamicSharedMemorySize,
                         AT2_SMEM_BYTES);
    cudaFuncSetAttribute(gemm_bf16split_v4, cudaFuncAttributeMaxDynamicSharedMemorySize,
                         GEMM_SMEM_BYTES);

    /* 0) split x; split+pad weights */
    {
        int n4 = (S_LEN * H_DIM) / 4;
        split4_kernel<<<(n4 + 255) / 256, 256>>>(hidden, xh, xl, n4);
        int tq = H_DIM * QKV_NP;
        wsplit_pad_kernel<<<(tq + 255) / 256, 256>>>(qkv_w, wqh, wql, QKV_N, QKV_NP, tq);
        int td = H_DIM * HD_NP;
        wsplit_pad_kernel<<<(td + 255) / 256, 256>>>(dense_w, wdh, wdl, H_DIM, HD_NP, td);
    }

    /* 1) qkv = x @ qkv_w (v4) */
    gemm_bf16split_v4<<<dim3(QKV_NP / 128, S_LEN / 128), 128, GEMM_SMEM_BYTES>>>(
        xh, xl, wqh, wql, qkv_p, S_LEN, QKV_N, QKV_NP, H_DIM);

    /* 2) RoPE + bf16 hi/lo split */
    rope_split_bf16_kernel<<<S_LEN, 256>>>(qkv_p, qh2, ql2, khT, klT, vh2, vl2);

    /* 3) flash attention, 128-row q tiles, longest-first */
    attn_mma_kernel<<<dim3(S_LEN / 128, NHEAD), 256, AT2_SMEM_BYTES>>>(
        qh2, ql2, khT, klT, vh2, vl2, ah, al);

    /* 4) out = attn @ dense_w (v4) */
    gemm_bf16split_v4<<<dim3(HD_NP / 128, S_LEN / 128), 128, GEMM_SMEM_BYTES>>>(
        ah, al, wdh, wdl, out, S_LEN, H_DIM, HD_NP, H_DIM);
}

// round 15
// speedup vs baseline: 1.0253x; 1.0253x over previous
#include <cuda_runtime.h>
#include <cuda_bf16.h>
#include <math.h>
#include <stdint.h>

#define S_LEN 2048
#define NHEAD 71
#define HDIM  64
#define H_DIM (NHEAD * HDIM)          /* 4544 */
#define QKV_N ((NHEAD + 2) * HDIM)    /* 4672 */
#define QKV_NP 4736                   /* padded to 128 */
#define HD_NP  4608                   /* padded to 128 */

/* ---- scratch (__device__ globals; no allocs allowed) ---- */
__device__ float g_qkv[(size_t)S_LEN * QKV_N];

__device__ __align__(256) __nv_bfloat16 g_xh[(size_t)S_LEN * H_DIM];
__device__ __align__(256) __nv_bfloat16 g_xl[(size_t)S_LEN * H_DIM];
__device__ __align__(256) __nv_bfloat16 g_wqh[(size_t)H_DIM * QKV_NP];
__device__ __align__(256) __nv_bfloat16 g_wql[(size_t)H_DIM * QKV_NP];
__device__ __align__(256) __nv_bfloat16 g_wdh[(size_t)H_DIM * HD_NP];
__device__ __align__(256) __nv_bfloat16 g_wdl[(size_t)H_DIM * HD_NP];
__device__ __align__(256) __nv_bfloat16 g_ah[(size_t)S_LEN * H_DIM];
__device__ __align__(256) __nv_bfloat16 g_al[(size_t)S_LEN * H_DIM];

__device__ __align__(256) __nv_bfloat16 g_qh2[(size_t)NHEAD * S_LEN * HDIM];
__device__ __align__(256) __nv_bfloat16 g_ql2[(size_t)NHEAD * S_LEN * HDIM];
__device__ __align__(256) __nv_bfloat16 g_khT[(size_t)HDIM * S_LEN];  /* [d][s] */
__device__ __align__(256) __nv_bfloat16 g_klT[(size_t)HDIM * S_LEN];
__device__ __align__(256) __nv_bfloat16 g_vh2[(size_t)S_LEN * HDIM];  /* [s][d] */
__device__ __align__(256) __nv_bfloat16 g_vl2[(size_t)S_LEN * HDIM];

/* =====================================================================
 * fp32 -> (bf16 hi, bf16 lo) split, vectorized by 4.
 * ===================================================================== */
__global__ void split4_kernel(const float* __restrict__ x,
                              __nv_bfloat16* __restrict__ hi,
                              __nv_bfloat16* __restrict__ lo,
                              int n4) {
    int i = blockIdx.x * blockDim.x + threadIdx.x;
    if (i >= n4) return;
    float4 v = ((const float4*)x)[i];
    float vv[4] = {v.x, v.y, v.z, v.w};
    __nv_bfloat16 h[4], l[4];
#pragma unroll
    for (int j = 0; j < 4; j++) {
        h[j] = __float2bfloat16(vv[j]);
        l[j] = __float2bfloat16(vv[j] - __bfloat162float(h[j]));
    }
    ((__nv_bfloat162*)hi)[2 * i + 0] = __nv_bfloat162(h[0], h[1]);
    ((__nv_bfloat162*)hi)[2 * i + 1] = __nv_bfloat162(h[2], h[3]);
    ((__nv_bfloat162*)lo)[2 * i + 0] = __nv_bfloat162(l[0], l[1]);
    ((__nv_bfloat162*)lo)[2 * i + 1] = __nv_bfloat162(l[2], l[3]);
}

/* split weights [K][N] -> [K][Npad] hi/lo, zero-pad n >= N */
__global__ void wsplit_pad_kernel(const float* __restrict__ W,
                                  __nv_bfloat16* __restrict__ Wh,
                                  __nv_bfloat16* __restrict__ Wl,
                                  int N, int Npad, int total) {
    int i = blockIdx.x * blockDim.x + threadIdx.x;
    if (i >= total) return;
    int k = i / Npad;
    int n = i - k * Npad;
    float v = (n < N) ? W[(size_t)k * N + n] : 0.0f;
    __nv_bfloat16 h = __float2bfloat16(v);
    __nv_bfloat16 l = __float2bfloat16(v - __bfloat162float(h));
    Wh[i] = h;
    Wl[i] = l;
}

/* ---- mma / async helpers ---- */
__device__ __forceinline__ void ldm_x4(uint32_t* r, uint32_t addr) {
    asm volatile("ldmatrix.sync.aligned.m8n8.x4.shared.b16 {%0,%1,%2,%3}, [%4];\n"
                 : "=r"(r[0]), "=r"(r[1]), "=r"(r[2]), "=r"(r[3]) : "r"(addr));
}
__device__ __forceinline__ void ldm_x4_t(uint32_t* r, uint32_t addr) {
    asm volatile("ldmatrix.sync.aligned.m8n8.x4.trans.shared.b16 {%0,%1,%2,%3}, [%4];\n"
                 : "=r"(r[0]), "=r"(r[1]), "=r"(r[2]), "=r"(r[3]) : "r"(addr));
}
__device__ __forceinline__ void mma_bf16(float* c, const uint32_t* a, const uint32_t* b) {
    asm volatile(
        "mma.sync.aligned.m16n8k16.row.col.f32.bf16.bf16.f32 "
        "{%0,%1,%2,%3}, {%4,%5,%6,%7}, {%8,%9}, {%0,%1,%2,%3};\n"
        : "+f"(c[0]), "+f"(c[1]), "+f"(c[2]), "+f"(c[3])
        : "r"(a[0]), "r"(a[1]), "r"(a[2]), "r"(a[3]), "r"(b[0]), "r"(b[1]));
}
__device__ __forceinline__ void cp16(uint32_t saddr, const void* gaddr) {
    asm volatile("cp.async.cg.shared.global [%0], [%1], 16;\n"
                 :: "r"(saddr), "l"(gaddr));
}
__device__ __forceinline__ void cp_commit() { asm volatile("cp.async.commit_group;\n"); }
template<int N> __device__ __forceinline__ void cp_wait() {
    asm volatile("cp.async.wait_group %0;\n" :: "n"(N));
}

/* FMA-only exp2 (no MUFU). abs err < 2e-5. */
__device__ __forceinline__ float exp2_fast(float x) {
    x = fmaxf(x, -120.0f);
    float fl = floorf(x);
    float f = x - fl;
    float p = fmaf(f, 1.540353e-4f, 1.3333558e-3f);
    p = fmaf(f, p, 9.6181291e-3f);
    p = fmaf(f, p, 5.5504109e-2f);
    p = fmaf(f, p, 2.4022651e-1f);
    p = fmaf(f, p, 6.9314718e-1f);
    p = fmaf(f, p, 1.0f);
    return __int_as_float(((int)fl + 127) << 23) * p;
}

/* =====================================================================
 * Split-bf16 GEMM v5: v4 tiling (BM=128 BN=128 BK=32, 4 warps, 64x64
 * warp tile, 2 CTAs/SM) with TERM-MAJOR mma issue: same-accumulator
 * reuse distance 1 -> 8 independent HMMAs, hiding tensor-pipe latency.
 * Per-accumulator addend order unchanged (hh, hl, lh) => bitwise same.
 * ===================================================================== */
#define APITCH 40
#define BPITCH 136
#define A_TILE (128 * APITCH)
#define B_TILE (32 * BPITCH)
#define OFF_AH 0
#define OFF_AL (A_TILE)
#define OFF_BH (2 * A_TILE)
#define OFF_BL (2 * A_TILE + B_TILE)
#define STAGE_ELEMS (2 * A_TILE + 2 * B_TILE)
#define GEMM_SMEM_BYTES (2 * STAGE_ELEMS * 2)

__global__ void __launch_bounds__(128, 2)
gemm_bf16split_v5(const __nv_bfloat16* __restrict__ Ah,
                  const __nv_bfloat16* __restrict__ Al,
                  const __nv_bfloat16* __restrict__ Bh,
                  const __nv_bfloat16* __restrict__ Bl,
                  float* __restrict__ C,
                  int M, int N, int Npad, int K) {
    extern __shared__ __nv_bfloat16 sm[];
    uint32_t sbase = (uint32_t)__cvta_generic_to_shared(sm);

    const int tid  = threadIdx.x;
    const int lane = tid & 31;
    const int wid  = tid >> 5;
    const int wm   = (wid & 1) * 64;
    const int wn   = (wid >> 1) * 64;
    const int rowBlk = blockIdx.y * 128;
    const int colBlk = blockIdx.x * 128;

    const int arA = tid >> 2;
    const int acA = (tid & 3) * 8;
    const int brB = tid >> 4;
    const int bcB = (tid & 15) * 8;

    const __nv_bfloat16* pAh = Ah + (size_t)(rowBlk + arA) * K + acA;
    const __nv_bfloat16* pAl = Al + (size_t)(rowBlk + arA) * K + acA;
    const __nv_bfloat16* pBh = Bh + (size_t)brB * Npad + colBlk + bcB;
    const __nv_bfloat16* pBl = Bl + (size_t)brB * Npad + colBlk + bcB;

    const uint32_t sAh = sbase + (uint32_t)(OFF_AH + arA * APITCH + acA) * 2;
    const uint32_t sAl = sbase + (uint32_t)(OFF_AL + arA * APITCH + acA) * 2;
    const uint32_t sBh = sbase + (uint32_t)(OFF_BH + brB * BPITCH + bcB) * 2;
    const uint32_t sBl = sbase + (uint32_t)(OFF_BL + brB * BPITCH + bcB) * 2;

    const int lr = lane & 15;
    const int lc = (lane >> 4) << 3;

    float acc[4][8][4];
#pragma unroll
    for (int mt = 0; mt < 4; mt++)
#pragma unroll
        for (int nt = 0; nt < 8; nt++)
#pragma unroll
            for (int r = 0; r < 4; r++) acc[mt][nt][r] = 0.0f;

    const int iters = K / 32;

    auto issue = [&](int it, int s) {
        uint32_t so = (uint32_t)(s * STAGE_ELEMS) * 2;
        int ko = it * 32;
#pragma unroll
        for (int i = 0; i < 4; i++) {
            cp16(sAh + so + (uint32_t)(i * 32 * APITCH) * 2, pAh + (size_t)i * 32 * K + ko);
            cp16(sAl + so + (uint32_t)(i * 32 * APITCH) * 2, pAl + (size_t)i * 32 * K + ko);
        }
#pragma unroll
        for (int i = 0; i < 4; i++) {
            cp16(sBh + so + (uint32_t)(i * 8 * BPITCH) * 2, pBh + (size_t)(i * 8 + ko) * Npad);
            cp16(sBl + so + (uint32_t)(i * 8 * BPITCH) * 2, pBl + (size_t)(i * 8 + ko) * Npad);
        }
        cp_commit();
    };

    issue(0, 0);

    for (int it = 0; it < iters; it++) {
        int s = it & 1;
        if (it + 1 < iters) {
            issue(it + 1, s ^ 1);
            cp_wait<1>();
        } else {
            cp_wait<0>();
        }
        __syncthreads();

        uint32_t sb = sbase + (uint32_t)(s * STAGE_ELEMS) * 2;
#pragma unroll
        for (int kk = 0; kk < 32; kk += 16) {
            uint32_t ah[4][4], al[4][4];
#pragma unroll
            for (int mt = 0; mt < 4; mt++) {
                uint32_t arow = (uint32_t)(wm + mt * 16 + lr);
                uint32_t acol = (uint32_t)(kk + lc);
                ldm_x4(ah[mt], sb + (uint32_t)(OFF_AH) * 2 + (arow * APITCH + acol) * 2);
                ldm_x4(al[mt], sb + (uint32_t)(OFF_AL) * 2 + (arow * APITCH + acol) * 2);
            }
#pragma unroll
            for (int nh = 0; nh < 4; nh++) {
                uint32_t bh[4], bl[4];
                uint32_t brow = (uint32_t)(kk + lr);
                uint32_t bcol = (uint32_t)(wn + nh * 16 + lc);
                ldm_x4_t(bh, sb + (uint32_t)(OFF_BH) * 2 + (brow * BPITCH + bcol) * 2);
                ldm_x4_t(bl, sb + (uint32_t)(OFF_BL) * 2 + (brow * BPITCH + bcol) * 2);
                /* term-major: 8 independent mmas between same-acc reuse */
#pragma unroll
                for (int mt = 0; mt < 4; mt++) {
                    mma_bf16(acc[mt][2 * nh + 0], ah[mt], &bh[0]);
                    mma_bf16(acc[mt][2 * nh + 1], ah[mt], &bh[2]);
                }
#pragma unroll
                for (int mt = 0; mt < 4; mt++) {
                    mma_bf16(acc[mt][2 * nh + 0], ah[mt], &bl[0]);
                    mma_bf16(acc[mt][2 * nh + 1], ah[mt], &bl[2]);
                }
#pragma unroll
                for (int mt = 0; mt < 4; mt++) {
                    mma_bf16(acc[mt][2 * nh + 0], al[mt], &bh[0]);
                    mma_bf16(acc[mt][2 * nh + 1], al[mt], &bh[2]);
                }
            }
        }
        __syncthreads();
    }

#pragma unroll
    for (int mt = 0; mt < 4; mt++) {
        int row = rowBlk + wm + mt * 16 + (lane >> 2);
#pragma unroll
        for (int nt = 0; nt < 8; nt++) {
            int col = colBlk + wn + nt * 8 + (lane & 3) * 2;
            if (col < N) {
                *(float2*)&C[(size_t)row * N + col] =
                    make_float2(acc[mt][nt][0], acc[mt][nt][1]);
                *(float2*)&C[(size_t)(row + 8) * N + col] =
                    make_float2(acc[mt][nt][2], acc[mt][nt][3]);
            }
        }
    }
}

/* =====================================================================
 * RoPE + split to bf16 hi/lo (unchanged).
 * ===================================================================== */
__global__ void rope_split_bf16_kernel(const float* __restrict__ qkv,
                                       __nv_bfloat16* __restrict__ qh,
                                       __nv_bfloat16* __restrict__ ql,
                                       __nv_bfloat16* __restrict__ khT,
                                       __nv_bfloat16* __restrict__ klT,
                                       __nv_bfloat16* __restrict__ vh,
                                       __nv_bfloat16* __restrict__ vl) {
    __shared__ float cs_s[32], sn_s[32];
    const int s = blockIdx.x;
    const float* row = qkv + (size_t)s * QKV_N;

    if (threadIdx.x < 32) {
        const float L2C = 13.28771237954945f / 32.0f;
        float inv = exp2f(-(float)threadIdx.x * L2C);
        float sn, cs;
        sincosf((float)s * inv, &sn, &cs);
        cs_s[threadIdx.x] = cs;
        sn_s[threadIdx.x] = sn;
    }
    __syncthreads();

    for (int col = threadIdx.x; col < QKV_N; col += blockDim.x) {
        const int h = col >> 6;
        const int d = col & 63;
        float val = row[col];
        float o;
        if (h < NHEAD + 1) {
            const int jj = d & 31;
            float other = (d < 32) ? -row[h * 64 + d + 32] : row[h * 64 + d - 32];
            o = val * cs_s[jj] + other * sn_s[jj];
        } else {
            o = val;
        }
        __nv_bfloat16 hi = __float2bfloat16(o);
        __nv_bfloat16 lo = __float2bfloat16(o - __bfloat162float(hi));
        if (h < NHEAD) {
            size_t idx = ((size_t)h * S_LEN + s) * HDIM + d;
            qh[idx] = hi; ql[idx] = lo;
        } else if (h == NHEAD) {
            size_t idx = (size_t)d * S_LEN + s;
            khT[idx] = hi; klT[idx] = lo;
        } else {
            size_t idx = (size_t)s * HDIM + d;
            vh[idx] = hi; vl[idx] = lo;
        }
    }
}

/* =====================================================================
 * Tensor-core flash attention (R12 proven version: 64-row q tiles).
 * ===================================================================== */
#define AT_PITCH 72
#define AT_TILE  (64 * AT_PITCH)
#define OFF_QH 0
#define OFF_QL (1 * AT_TILE)
#define OFF_KH (2 * AT_TILE)
#define OFF_KL (3 * AT_TILE)
#define OFF_VH (4 * AT_TILE)
#define OFF_VL (5 * AT_TILE)
#define AT_SMEM_BYTES (6 * AT_TILE * 2)

__global__ void __launch_bounds__(128)
attn_mma_kernel(const __nv_bfloat16* __restrict__ Qh,
                const __nv_bfloat16* __restrict__ Ql,
                const __nv_bfloat16* __restrict__ KhT,
                const __nv_bfloat16* __restrict__ KlT,
                const __nv_bfloat16* __restrict__ Vh,
                const __nv_bfloat16* __restrict__ Vl,
                __nv_bfloat16* __restrict__ Oh,
                __nv_bfloat16* __restrict__ Ol) {
    extern __shared__ unsigned char sraw[];
    __nv_bfloat16* S = (__nv_bfloat16*)sraw;
    uint32_t sbase = (uint32_t)__cvta_generic_to_shared(S);

    const int tid  = threadIdx.x;
    const int lane = tid & 31;
    const int w    = tid >> 5;
    const int qt   = gridDim.x - 1 - blockIdx.x;   /* longest-first */
    const int h    = blockIdx.y;
    const int qs0  = qt * 64;

    const int lr = lane & 15;
    const int lc = (lane >> 4) << 3;
    const int qr = lane >> 2;
    const int qc = (lane & 3) * 2;

    {
        const __nv_bfloat16* qhg = Qh + ((size_t)h * S_LEN + qs0) * HDIM;
        const __nv_bfloat16* qlg = Ql + ((size_t)h * S_LEN + qs0) * HDIM;
        for (int i = tid; i < 512; i += 128) {
            int r = i >> 3, c = (i & 7) * 8;
            *(uint4*)&S[OFF_QH + r * AT_PITCH + c] = *(const uint4*)&qhg[r * 64 + c];
            *(uint4*)&S[OFF_QL + r * AT_PITCH + c] = *(const uint4*)&qlg[r * 64 + c];
        }
    }

    float m1 = -1e30f, m2 = -1e30f, l1 = 0.0f, l2 = 0.0f;
    float o[8][4];
#pragma unroll
    for (int nt = 0; nt < 8; nt++)
#pragma unroll
        for (int j = 0; j < 4; j++) o[nt][j] = 0.0f;

    const float SC = 0.125f * 1.4426950408889634f;
    const int row1 = w * 16 + qr;
    const int row2 = row1 + 8;

    for (int jt = 0; jt <= qt; jt++) {
        for (int i = tid; i < 512; i += 128) {
            int r = i >> 3, c = (i & 7) * 8;
            *(uint4*)&S[OFF_KH + r * AT_PITCH + c] =
                *(const uint4*)&KhT[(size_t)r * S_LEN + jt * 64 + c];
            *(uint4*)&S[OFF_KL + r * AT_PITCH + c] =
                *(const uint4*)&KlT[(size_t)r * S_LEN + jt * 64 + c];
            *(uint4*)&S[OFF_VH + r * AT_PITCH + c] =
                *(const uint4*)&Vh[(size_t)(jt * 64 + r) * 64 + c];
            *(uint4*)&S[OFF_VL + r * AT_PITCH + c] =
                *(const uint4*)&Vl[(size_t)(jt * 64 + r) * 64 + c];
        }
        __syncthreads();

        float s[8][4];
#pragma unroll
        for (int nt = 0; nt < 8; nt++)
#pragma unroll
            for (int j = 0; j < 4; j++) s[nt][j] = 0.0f;

#pragma unroll
        for (int kk = 0; kk < 64; kk += 16) {
            uint32_t qfh[4], qfl[4];
            ldm_x4(qfh, sbase + (uint32_t)(OFF_QH + (w * 16 + lr) * AT_PITCH + kk + lc) * 2);
            ldm_x4(qfl, sbase + (uint32_t)(OFF_QL + (w * 16 + lr) * AT_PITCH + kk + lc) * 2);
#pragma unroll
            for (int half = 0; half < 4; half++) {
                uint32_t bh[2][2], bl[2][2], r4[4];
                ldm_x4_t(r4, sbase + (uint32_t)(OFF_KH + (kk + lr) * AT_PITCH + half * 16 + lc) * 2);
                bh[0][0] = r4[0]; bh[0][1] = r4[1]; bh[1][0] = r4[2]; bh[1][1] = r4[3];
                ldm_x4_t(r4, sbase + (uint32_t)(OFF_KL + (kk + lr) * AT_PITCH + half * 16 + lc) * 2);
                bl[0][0] = r4[0]; bl[0][1] = r4[1]; bl[1][0] = r4[2]; bl[1][1] = r4[3];
#pragma unroll
                for (int t = 0; t < 2; t++) {
                    int nt = half * 2 + t;
                    mma_bf16(s[nt], qfh, bh[t]);
                    mma_bf16(s[nt], qfh, bl[t]);
                    mma_bf16(s[nt], qfl, bh[t]);
                }
            }
        }

#pragma unroll
        for (int nt = 0; nt < 8; nt++)
#pragma unroll
            for (int j = 0; j < 4; j++) s[nt][j] *= SC;

        if (jt == qt) {
#pragma unroll
            for (int nt = 0; nt < 8; nt++) {
                int c0 = nt * 8 + qc;
                if (c0     > row1) s[nt][0] = -1e30f;
                if (c0 + 1 > row1) s[nt][1] = -1e30f;
                if (c0     > row2) s[nt][2] = -1e30f;
                if (c0 + 1 > row2) s[nt][3] = -1e30f;
            }
        }

        float pm1 = -1e30f, pm2 = -1e30f;
#pragma unroll
        for (int nt = 0; nt < 8; nt++) {
            pm1 = fmaxf(pm1, fmaxf(s[nt][0], s[nt][1]));
            pm2 = fmaxf(pm2, fmaxf(s[nt][2], s[nt][3]));
        }
        pm1 = fmaxf(pm1, __shfl_xor_sync(0xffffffff, pm1, 1));
        pm1 = fmaxf(pm1, __shfl_xor_sync(0xffffffff, pm1, 2));
        pm2 = fmaxf(pm2, __shfl_xor_sync(0xffffffff, pm2, 1));
        pm2 = fmaxf(pm2, __shfl_xor_sync(0xffffffff, pm2, 2));

        float mn1 = fmaxf(m1, pm1), mn2 = fmaxf(m2, pm2);
        float rs1 = exp2_fast(m1 - mn1), rs2 = exp2_fast(m2 - mn2);
        m1 = mn1; m2 = mn2;

        float sum1 = 0.0f, sum2 = 0.0f;
        uint32_t phA[8], phB[8], plA[8], plB[8];
#pragma unroll
        for (int nt = 0; nt < 8; nt++) {
            float e0 = exp2_fast(s[nt][0] - m1);
            float e1 = exp2_fast(s[nt][1] - m1);
            float e2 = exp2_fast(s[nt][2] - m2);
            float e3 = exp2_fast(s[nt][3] - m2);
            sum1 += e0 + e1;
            sum2 += e2 + e3;
            __nv_bfloat162 h01 = __floats2bfloat162_rn(e0, e1);
            __nv_bfloat162 h23 = __floats2bfloat162_rn(e2, e3);
            float r0 = e0 - __bfloat162float(h01.x);
            float r1 = e1 - __bfloat162float(h01.y);
            float r2 = e2 - __bfloat162float(h23.x);
            float r3 = e3 - __bfloat162float(h23.y);
            __nv_bfloat162 l01 = __floats2bfloat162_rn(r0, r1);
            __nv_bfloat162 l23 = __floats2bfloat162_rn(r2, r3);
            phA[nt] = *(uint32_t*)&h01;  phB[nt] = *(uint32_t*)&h23;
            plA[nt] = *(uint32_t*)&l01;  plB[nt] = *(uint32_t*)&l23;
        }
        sum1 += __shfl_xor_sync(0xffffffff, sum1, 1);
        sum1 += __shfl_xor_sync(0xffffffff, sum1, 2);
        sum2 += __shfl_xor_sync(0xffffffff, sum2, 1);
        sum2 += __shfl_xor_sync(0xffffffff, sum2, 2);
        l1 = l1 * rs1 + sum1;
        l2 = l2 * rs2 + sum2;

#pragma unroll
        for (int nt = 0; nt < 8; nt++) {
            o[nt][0] *= rs1; o[nt][1] *= rs1;
            o[nt][2] *= rs2; o[nt][3] *= rs2;
        }

#pragma unroll
        for (int t = 0; t < 4; t++) {
            uint32_t aH[4] = {phA[2 * t], phB[2 * t], phA[2 * t + 1], phB[2 * t + 1]};
            uint32_t aL[4] = {plA[2 * t], plB[2 * t], plA[2 * t + 1], plB[2 * t + 1]};
#pragma unroll
            for (int half = 0; half < 4; half++) {
                uint32_t bh[2][2], bl[2][2], r4[4];
                ldm_x4_t(r4, sbase + (uint32_t)(OFF_VH + (t * 16 + lr) * AT_PITCH + half * 16 + lc) * 2);
                bh[0][0] = r4[0]; bh[0][1] = r4[1]; bh[1][0] = r4[2]; bh[1][1] = r4[3];
                ldm_x4_t(r4, sbase + (uint32_t)(OFF_VL + (t * 16 + lr) * AT_PITCH + half * 16 + lc) * 2);
                bl[0][0] = r4[0]; bl[0][1] = r4[1]; bl[1][0] = r4[2]; bl[1][1] = r4[3];
#pragma unroll
                for (int tt = 0; tt < 2; tt++) {
                    int nt = half * 2 + tt;
                    mma_bf16(o[nt], aH, bh[tt]);
                    mma_bf16(o[nt], aL, bh[tt]);
                    mma_bf16(o[nt], aH, bl[tt]);
                }
            }
        }
        __syncthreads();
    }

    float inv1 = 1.0f / l1, inv2 = 1.0f / l2;
    int gr1 = qs0 + row1, gr2 = qs0 + row2;
#pragma unroll
    for (int nt = 0; nt < 8; nt++) {
        int col = h * 64 + nt * 8 + qc;
        float v0 = o[nt][0] * inv1, v1 = o[nt][1] * inv1;
        float v2 = o[nt][2] * inv2, v3 = o[nt][3] * inv2;
        __nv_bfloat162 h01 = __floats2bfloat162_rn(v0, v1);
        __nv_bfloat162 h23 = __floats2bfloat162_rn(v2, v3);
        __nv_bfloat162 l01 = __floats2bfloat162_rn(v0 - __bfloat162float(h01.x),
                                                   v1 - __bfloat162float(h01.y));
        __nv_bfloat162 l23 = __floats2bfloat162_rn(v2 - __bfloat162float(h23.x),
                                                   v3 - __bfloat162float(h23.y));
        *(uint32_t*)&Oh[(size_t)gr1 * H_DIM + col] = *(uint32_t*)&h01;
        *(uint32_t*)&Ol[(size_t)gr1 * H_DIM + col] = *(uint32_t*)&l01;
        *(uint32_t*)&Oh[(size_t)gr2 * H_DIM + col] = *(uint32_t*)&h23;
        *(uint32_t*)&Ol[(size_t)gr2 * H_DIM + col] = *(uint32_t*)&l23;
    }
}

/* ===================================================================== */
extern "C" void kernel_launch(void* const* d_in, const int* in_sizes, int n_in,
                              void* d_out, int out_size) {
    const float* hidden  = (const float*)d_in[0];
    const float* qkv_w   = (const float*)d_in[2];
    const float* dense_w = (const float*)d_in[3];
    float* out = (float*)d_out;

    float* qkv_p;
    cudaGetSymbolAddress((void**)&qkv_p, g_qkv);

    __nv_bfloat16 *xh, *xl, *wqh, *wql, *wdh, *wdl, *ah, *al;
    __nv_bfloat16 *qh2, *ql2, *khT, *klT, *vh2, *vl2;
    cudaGetSymbolAddress((void**)&xh,  g_xh);
    cudaGetSymbolAddress((void**)&xl,  g_xl);
    cudaGetSymbolAddress((void**)&wqh, g_wqh);
    cudaGetSymbolAddress((void**)&wql, g_wql);
    cudaGetSymbolAddress((void**)&wdh, g_wdh);
    cudaGetSymbolAddress((void**)&wdl, g_wdl);
    cudaGetSymbolAddress((void**)&ah,  g_ah);
    cudaGetSymbolAddress((void**)&al,  g_al);
    cudaGetSymbolAddress((void**)&qh2, g_qh2);
    cudaGetSymbolAddress((void**)&ql2, g_ql2);
    cudaGetSymbolAddress((void**)&khT, g_khT);
    cudaGetSymbolAddress((void**)&klT, g_klT);
    cudaGetSymbolAddress((void**)&vh2, g_vh2);
    cudaGetSymbolAddress((void**)&vl2, g_vl2);

    cudaFuncSetAttribute(attn_mma_kernel, cudaFuncAttributeMaxDynamicSharedMemorySize,
                         AT_SMEM_BYTES);
    cudaFuncSetAttribute(gemm_bf16split_v5, cudaFuncAttributeMaxDynamicSharedMemorySize,
                         GEMM_SMEM_BYTES);

    /* 0) split x; split+pad weights */
    {
        int n4 = (S_LEN * H_DIM) / 4;
        split4_kernel<<<(n4 + 255) / 256, 256>>>(hidden, xh, xl, n4);
        int tq = H_DIM * QKV_NP;
        wsplit_pad_kernel<<<(tq + 255) / 256, 256>>>(qkv_w, wqh, wql, QKV_N, QKV_NP, tq);
        int td = H_DIM * HD_NP;
        wsplit_pad_kernel<<<(td + 255) / 256, 256>>>(dense_w, wdh, wdl, H_DIM, HD_NP, td);
    }

    /* 1) qkv = x @ qkv_w (v5) */
    gemm_bf16split_v5<<<dim3(QKV_NP / 128, S_LEN / 128), 128, GEMM_SMEM_BYTES>>>(
        xh, xl, wqh, wql, qkv_p, S_LEN, QKV_N, QKV_NP, H_DIM);

    /* 2) RoPE + bf16 hi/lo split */
    rope_split_bf16_kernel<<<S_LEN, 256>>>(qkv_p, qh2, ql2, khT, klT, vh2, vl2);

    /* 3) flash attention (64-row q tiles, longest-first) */
    attn_mma_kernel<<<dim3(S_LEN / 64, NHEAD), 128, AT_SMEM_BYTES>>>(
        qh2, ql2, khT, klT, vh2, vl2, ah, al);

    /* 4) out = attn @ dense_w (v5) */
    gemm_bf16split_v5<<<dim3(HD_NP / 128, S_LEN / 128), 128, GEMM_SMEM_BYTES>>>(
        ah, al, wdh, wdl, out, S_LEN, H_DIM, HD_NP, H_DIM);
}

// round 16
// speedup vs baseline: 1.0518x; 1.0258x over previous
#include <cuda_runtime.h>
#include <cuda_bf16.h>
#include <math.h>
#include <stdint.h>

#define S_LEN 2048
#define NHEAD 71
#define HDIM  64
#define H_DIM (NHEAD * HDIM)          /* 4544 */
#define QKV_N ((NHEAD + 2) * HDIM)    /* 4672 */
#define QKV_NP 4736                   /* padded to 128 */
#define HD_NP  4608                   /* padded to 128 */

/* ---- scratch (__device__ globals; no allocs allowed) ---- */
__device__ float g_qkv[(size_t)S_LEN * QKV_N];

__device__ __align__(256) __nv_bfloat16 g_xh[(size_t)S_LEN * H_DIM];
__device__ __align__(256) __nv_bfloat16 g_xl[(size_t)S_LEN * H_DIM];
__device__ __align__(256) __nv_bfloat16 g_wqh[(size_t)H_DIM * QKV_NP];
__device__ __align__(256) __nv_bfloat16 g_wql[(size_t)H_DIM * QKV_NP];
__device__ __align__(256) __nv_bfloat16 g_wdh[(size_t)H_DIM * HD_NP];
__device__ __align__(256) __nv_bfloat16 g_wdl[(size_t)H_DIM * HD_NP];
__device__ __align__(256) __nv_bfloat16 g_ah[(size_t)S_LEN * H_DIM];
__device__ __align__(256) __nv_bfloat16 g_al[(size_t)S_LEN * H_DIM];

__device__ __align__(256) __nv_bfloat16 g_qh2[(size_t)NHEAD * S_LEN * HDIM];
__device__ __align__(256) __nv_bfloat16 g_ql2[(size_t)NHEAD * S_LEN * HDIM];
__device__ __align__(256) __nv_bfloat16 g_khT[(size_t)HDIM * S_LEN];  /* [d][s] */
__device__ __align__(256) __nv_bfloat16 g_klT[(size_t)HDIM * S_LEN];
__device__ __align__(256) __nv_bfloat16 g_vh2[(size_t)S_LEN * HDIM];  /* [s][d] */
__device__ __align__(256) __nv_bfloat16 g_vl2[(size_t)S_LEN * HDIM];

/* =====================================================================
 * fp32 -> (bf16 hi, bf16 lo) split, vectorized by 4.
 * ===================================================================== */
__global__ void split4_kernel(const float* __restrict__ x,
                              __nv_bfloat16* __restrict__ hi,
                              __nv_bfloat16* __restrict__ lo,
                              int n4) {
    int i = blockIdx.x * blockDim.x + threadIdx.x;
    if (i >= n4) return;
    float4 v = ((const float4*)x)[i];
    float vv[4] = {v.x, v.y, v.z, v.w};
    __nv_bfloat16 h[4], l[4];
#pragma unroll
    for (int j = 0; j < 4; j++) {
        h[j] = __float2bfloat16(vv[j]);
        l[j] = __float2bfloat16(vv[j] - __bfloat162float(h[j]));
    }
    ((__nv_bfloat162*)hi)[2 * i + 0] = __nv_bfloat162(h[0], h[1]);
    ((__nv_bfloat162*)hi)[2 * i + 1] = __nv_bfloat162(h[2], h[3]);
    ((__nv_bfloat162*)lo)[2 * i + 0] = __nv_bfloat162(l[0], l[1]);
    ((__nv_bfloat162*)lo)[2 * i + 1] = __nv_bfloat162(l[2], l[3]);
}

/* split weights [K][N] -> [K][Npad] hi/lo, zero-pad n >= N */
__global__ void wsplit_pad_kernel(const float* __restrict__ W,
                                  __nv_bfloat16* __restrict__ Wh,
                                  __nv_bfloat16* __restrict__ Wl,
                                  int N, int Npad, int total) {
    int i = blockIdx.x * blockDim.x + threadIdx.x;
    if (i >= total) return;
    int k = i / Npad;
    int n = i - k * Npad;
    float v = (n < N) ? W[(size_t)k * N + n] : 0.0f;
    __nv_bfloat16 h = __float2bfloat16(v);
    __nv_bfloat16 l = __float2bfloat16(v - __bfloat162float(h));
    Wh[i] = h;
    Wl[i] = l;
}

/* ---- mma / async helpers ---- */
__device__ __forceinline__ void ldm_x4(uint32_t* r, uint32_t addr) {
    asm volatile("ldmatrix.sync.aligned.m8n8.x4.shared.b16 {%0,%1,%2,%3}, [%4];\n"
                 : "=r"(r[0]), "=r"(r[1]), "=r"(r[2]), "=r"(r[3]) : "r"(addr));
}
__device__ __forceinline__ void ldm_x4_t(uint32_t* r, uint32_t addr) {
    asm volatile("ldmatrix.sync.aligned.m8n8.x4.trans.shared.b16 {%0,%1,%2,%3}, [%4];\n"
                 : "=r"(r[0]), "=r"(r[1]), "=r"(r[2]), "=r"(r[3]) : "r"(addr));
}
__device__ __forceinline__ void mma_bf16(float* c, const uint32_t* a, const uint32_t* b) {
    asm volatile(
        "mma.sync.aligned.m16n8k16.row.col.f32.bf16.bf16.f32 "
        "{%0,%1,%2,%3}, {%4,%5,%6,%7}, {%8,%9}, {%0,%1,%2,%3};\n"
        : "+f"(c[0]), "+f"(c[1]), "+f"(c[2]), "+f"(c[3])
        : "r"(a[0]), "r"(a[1]), "r"(a[2]), "r"(a[3]), "r"(b[0]), "r"(b[1]));
}
__device__ __forceinline__ void cp16(uint32_t saddr, const void* gaddr) {
    asm volatile("cp.async.cg.shared.global [%0], [%1], 16;\n"
                 :: "r"(saddr), "l"(gaddr));
}
__device__ __forceinline__ void cp_commit() { asm volatile("cp.async.commit_group;\n"); }
template<int N> __device__ __forceinline__ void cp_wait() {
    asm volatile("cp.async.wait_group %0;\n" :: "n"(N));
}

/* FMA-only exp2 (no MUFU). abs err < 2e-5. */
__device__ __forceinline__ float exp2_fast(float x) {
    x = fmaxf(x, -120.0f);
    float fl = floorf(x);
    float f = x - fl;
    float p = fmaf(f, 1.540353e-4f, 1.3333558e-3f);
    p = fmaf(f, p, 9.6181291e-3f);
    p = fmaf(f, p, 5.5504109e-2f);
    p = fmaf(f, p, 2.4022651e-1f);
    p = fmaf(f, p, 6.9314718e-1f);
    p = fmaf(f, p, 1.0f);
    return __int_as_float(((int)fl + 127) << 23) * p;
}

/* =====================================================================
 * Split-bf16 GEMM v6: v4/v5 tiling (BM=128 BN=128 BK=32, 4 warps,
 * 64x64 warp tile, 2 CTAs/SM) with a 3-STAGE cp.async pipeline and
 * ONE barrier per K-iteration (issue moved after the barrier; buffer
 * at distance 3 is provably idle). 2 iterations of load slack.
 * ===================================================================== */
#define APITCH 40
#define BPITCH 136
#define A_TILE (128 * APITCH)
#define B_TILE (32 * BPITCH)
#define OFF_AH 0
#define OFF_AL (A_TILE)
#define OFF_BH (2 * A_TILE)
#define OFF_BL (2 * A_TILE + B_TILE)
#define STAGE_ELEMS (2 * A_TILE + 2 * B_TILE)      /* 18944 elems = 37888 B */
#define GEMM_SMEM_BYTES (3 * STAGE_ELEMS * 2)      /* 113664 B */

__global__ void __launch_bounds__(128, 2)
gemm_bf16split_v6(const __nv_bfloat16* __restrict__ Ah,
                  const __nv_bfloat16* __restrict__ Al,
                  const __nv_bfloat16* __restrict__ Bh,
                  const __nv_bfloat16* __restrict__ Bl,
                  float* __restrict__ C,
                  int M, int N, int Npad, int K) {
    extern __shared__ __nv_bfloat16 sm[];
    uint32_t sbase = (uint32_t)__cvta_generic_to_shared(sm);

    const int tid  = threadIdx.x;
    const int lane = tid & 31;
    const int wid  = tid >> 5;
    const int wm   = (wid & 1) * 64;
    const int wn   = (wid >> 1) * 64;
    const int rowBlk = blockIdx.y * 128;
    const int colBlk = blockIdx.x * 128;

    const int arA = tid >> 2;
    const int acA = (tid & 3) * 8;
    const int brB = tid >> 4;
    const int bcB = (tid & 15) * 8;

    const __nv_bfloat16* pAh = Ah + (size_t)(rowBlk + arA) * K + acA;
    const __nv_bfloat16* pAl = Al + (size_t)(rowBlk + arA) * K + acA;
    const __nv_bfloat16* pBh = Bh + (size_t)brB * Npad + colBlk + bcB;
    const __nv_bfloat16* pBl = Bl + (size_t)brB * Npad + colBlk + bcB;

    const uint32_t sAh = sbase + (uint32_t)(OFF_AH + arA * APITCH + acA) * 2;
    const uint32_t sAl = sbase + (uint32_t)(OFF_AL + arA * APITCH + acA) * 2;
    const uint32_t sBh = sbase + (uint32_t)(OFF_BH + brB * BPITCH + bcB) * 2;
    const uint32_t sBl = sbase + (uint32_t)(OFF_BL + brB * BPITCH + bcB) * 2;

    const int lr = lane & 15;
    const int lc = (lane >> 4) << 3;

    float acc[4][8][4];
#pragma unroll
    for (int mt = 0; mt < 4; mt++)
#pragma unroll
        for (int nt = 0; nt < 8; nt++)
#pragma unroll
            for (int r = 0; r < 4; r++) acc[mt][nt][r] = 0.0f;

    const int iters = K / 32;

    auto issue = [&](int it, int s) {
        uint32_t so = (uint32_t)(s * STAGE_ELEMS) * 2;
        int ko = it * 32;
#pragma unroll
        for (int i = 0; i < 4; i++) {
            cp16(sAh + so + (uint32_t)(i * 32 * APITCH) * 2, pAh + (size_t)i * 32 * K + ko);
            cp16(sAl + so + (uint32_t)(i * 32 * APITCH) * 2, pAl + (size_t)i * 32 * K + ko);
        }
#pragma unroll
        for (int i = 0; i < 4; i++) {
            cp16(sBh + so + (uint32_t)(i * 8 * BPITCH) * 2, pBh + (size_t)(i * 8 + ko) * Npad);
            cp16(sBl + so + (uint32_t)(i * 8 * BPITCH) * 2, pBl + (size_t)(i * 8 + ko) * Npad);
        }
        cp_commit();
    };

    /* prologue: fill stages 0, 1 */
    issue(0, 0);
    if (iters > 1) issue(1, 1);

    int buf = 0;
    for (int it = 0; it < iters; it++) {
        /* ensure the group for chunk `it` has landed */
        if (it + 1 < iters) cp_wait<1>(); else cp_wait<0>();
        __syncthreads();   /* everyone past iter it-1; buf (it+2)%3 is idle */

        if (it + 2 < iters) {
            int nb = buf + 2;
            if (nb >= 3) nb -= 3;
            issue(it + 2, nb);
        }

        uint32_t sb = sbase + (uint32_t)(buf * STAGE_ELEMS) * 2;
#pragma unroll
        for (int kk = 0; kk < 32; kk += 16) {
            uint32_t ah[4][4], al[4][4];
#pragma unroll
            for (int mt = 0; mt < 4; mt++) {
                uint32_t arow = (uint32_t)(wm + mt * 16 + lr);
                uint32_t acol = (uint32_t)(kk + lc);
                ldm_x4(ah[mt], sb + (uint32_t)(OFF_AH) * 2 + (arow * APITCH + acol) * 2);
                ldm_x4(al[mt], sb + (uint32_t)(OFF_AL) * 2 + (arow * APITCH + acol) * 2);
            }
#pragma unroll
            for (int nh = 0; nh < 4; nh++) {
                uint32_t bh[4], bl[4];
                uint32_t brow = (uint32_t)(kk + lr);
                uint32_t bcol = (uint32_t)(wn + nh * 16 + lc);
                ldm_x4_t(bh, sb + (uint32_t)(OFF_BH) * 2 + (brow * BPITCH + bcol) * 2);
                ldm_x4_t(bl, sb + (uint32_t)(OFF_BL) * 2 + (brow * BPITCH + bcol) * 2);
#pragma unroll
                for (int mt = 0; mt < 4; mt++) {
                    mma_bf16(acc[mt][2 * nh + 0], ah[mt], &bh[0]);
                    mma_bf16(acc[mt][2 * nh + 1], ah[mt], &bh[2]);
                }
#pragma unroll
                for (int mt = 0; mt < 4; mt++) {
                    mma_bf16(acc[mt][2 * nh + 0], ah[mt], &bl[0]);
                    mma_bf16(acc[mt][2 * nh + 1], ah[mt], &bl[2]);
                }
#pragma unroll
                for (int mt = 0; mt < 4; mt++) {
                    mma_bf16(acc[mt][2 * nh + 0], al[mt], &bh[0]);
                    mma_bf16(acc[mt][2 * nh + 1], al[mt], &bh[2]);
                }
            }
        }
        buf = (buf + 1 == 3) ? 0 : buf + 1;
    }

#pragma unroll
    for (int mt = 0; mt < 4; mt++) {
        int row = rowBlk + wm + mt * 16 + (lane >> 2);
#pragma unroll
        for (int nt = 0; nt < 8; nt++) {
            int col = colBlk + wn + nt * 8 + (lane & 3) * 2;
            if (col < N) {
                *(float2*)&C[(size_t)row * N + col] =
                    make_float2(acc[mt][nt][0], acc[mt][nt][1]);
                *(float2*)&C[(size_t)(row + 8) * N + col] =
                    make_float2(acc[mt][nt][2], acc[mt][nt][3]);
            }
        }
    }
}

/* =====================================================================
 * RoPE + split to bf16 hi/lo (unchanged).
 * ===================================================================== */
__global__ void rope_split_bf16_kernel(const float* __restrict__ qkv,
                                       __nv_bfloat16* __restrict__ qh,
                                       __nv_bfloat16* __restrict__ ql,
                                       __nv_bfloat16* __restrict__ khT,
                                       __nv_bfloat16* __restrict__ klT,
                                       __nv_bfloat16* __restrict__ vh,
                                       __nv_bfloat16* __restrict__ vl) {
    __shared__ float cs_s[32], sn_s[32];
    const int s = blockIdx.x;
    const float* row = qkv + (size_t)s * QKV_N;

    if (threadIdx.x < 32) {
        const float L2C = 13.28771237954945f / 32.0f;
        float inv = exp2f(-(float)threadIdx.x * L2C);
        float sn, cs;
        sincosf((float)s * inv, &sn, &cs);
        cs_s[threadIdx.x] = cs;
        sn_s[threadIdx.x] = sn;
    }
    __syncthreads();

    for (int col = threadIdx.x; col < QKV_N; col += blockDim.x) {
        const int h = col >> 6;
        const int d = col & 63;
        float val = row[col];
        float o;
        if (h < NHEAD + 1) {
            const int jj = d & 31;
            float other = (d < 32) ? -row[h * 64 + d + 32] : row[h * 64 + d - 32];
            o = val * cs_s[jj] + other * sn_s[jj];
        } else {
            o = val;
        }
        __nv_bfloat16 hi = __float2bfloat16(o);
        __nv_bfloat16 lo = __float2bfloat16(o - __bfloat162float(hi));
        if (h < NHEAD) {
            size_t idx = ((size_t)h * S_LEN + s) * HDIM + d;
            qh[idx] = hi; ql[idx] = lo;
        } else if (h == NHEAD) {
            size_t idx = (size_t)d * S_LEN + s;
            khT[idx] = hi; klT[idx] = lo;
        } else {
            size_t idx = (size_t)s * HDIM + d;
            vh[idx] = hi; vl[idx] = lo;
        }
    }
}

/* =====================================================================
 * Tensor-core flash attention (64-row q tiles, longest-first; proven).
 * ===================================================================== */
#define AT_PITCH 72
#define AT_TILE  (64 * AT_PITCH)
#define OFF_QH 0
#define OFF_QL (1 * AT_TILE)
#define OFF_KH (2 * AT_TILE)
#define OFF_KL (3 * AT_TILE)
#define OFF_VH (4 * AT_TILE)
#define OFF_VL (5 * AT_TILE)
#define AT_SMEM_BYTES (6 * AT_TILE * 2)

__global__ void __launch_bounds__(128)
attn_mma_kernel(const __nv_bfloat16* __restrict__ Qh,
                const __nv_bfloat16* __restrict__ Ql,
                const __nv_bfloat16* __restrict__ KhT,
                const __nv_bfloat16* __restrict__ KlT,
                const __nv_bfloat16* __restrict__ Vh,
                const __nv_bfloat16* __restrict__ Vl,
                __nv_bfloat16* __restrict__ Oh,
                __nv_bfloat16* __restrict__ Ol) {
    extern __shared__ unsigned char sraw[];
    __nv_bfloat16* S = (__nv_bfloat16*)sraw;
    uint32_t sbase = (uint32_t)__cvta_generic_to_shared(S);

    const int tid  = threadIdx.x;
    const int lane = tid & 31;
    const int w    = tid >> 5;
    const int qt   = gridDim.x - 1 - blockIdx.x;   /* longest-first */
    const int h    = blockIdx.y;
    const int qs0  = qt * 64;

    const int lr = lane & 15;
    const int lc = (lane >> 4) << 3;
    const int qr = lane >> 2;
    const int qc = (lane & 3) * 2;

    {
        const __nv_bfloat16* qhg = Qh + ((size_t)h * S_LEN + qs0) * HDIM;
        const __nv_bfloat16* qlg = Ql + ((size_t)h * S_LEN + qs0) * HDIM;
        for (int i = tid; i < 512; i += 128) {
            int r = i >> 3, c = (i & 7) * 8;
            *(uint4*)&S[OFF_QH + r * AT_PITCH + c] = *(const uint4*)&qhg[r * 64 + c];
            *(uint4*)&S[OFF_QL + r * AT_PITCH + c] = *(const uint4*)&qlg[r * 64 + c];
        }
    }

    float m1 = -1e30f, m2 = -1e30f, l1 = 0.0f, l2 = 0.0f;
    float o[8][4];
#pragma unroll
    for (int nt = 0; nt < 8; nt++)
#pragma unroll
        for (int j = 0; j < 4; j++) o[nt][j] = 0.0f;

    const float SC = 0.125f * 1.4426950408889634f;
    const int row1 = w * 16 + qr;
    const int row2 = row1 + 8;

    for (int jt = 0; jt <= qt; jt++) {
        for (int i = tid; i < 512; i += 128) {
            int r = i >> 3, c = (i & 7) * 8;
            *(uint4*)&S[OFF_KH + r * AT_PITCH + c] =
                *(const uint4*)&KhT[(size_t)r * S_LEN + jt * 64 + c];
            *(uint4*)&S[OFF_KL + r * AT_PITCH + c] =
                *(const uint4*)&KlT[(size_t)r * S_LEN + jt * 64 + c];
            *(uint4*)&S[OFF_VH + r * AT_PITCH + c] =
                *(const uint4*)&Vh[(size_t)(jt * 64 + r) * 64 + c];
            *(uint4*)&S[OFF_VL + r * AT_PITCH + c] =
                *(const uint4*)&Vl[(size_t)(jt * 64 + r) * 64 + c];
        }
        __syncthreads();

        float s[8][4];
#pragma unroll
        for (int nt = 0; nt < 8; nt++)
#pragma unroll
            for (int j = 0; j < 4; j++) s[nt][j] = 0.0f;

#pragma unroll
        for (int kk = 0; kk < 64; kk += 16) {
            uint32_t qfh[4], qfl[4];
            ldm_x4(qfh, sbase + (uint32_t)(OFF_QH + (w * 16 + lr) * AT_PITCH + kk + lc) * 2);
            ldm_x4(qfl, sbase + (uint32_t)(OFF_QL + (w * 16 + lr) * AT_PITCH + kk + lc) * 2);
#pragma unroll
            for (int half = 0; half < 4; half++) {
                uint32_t bh[2][2], bl[2][2], r4[4];
                ldm_x4_t(r4, sbase + (uint32_t)(OFF_KH + (kk + lr) * AT_PITCH + half * 16 + lc) * 2);
                bh[0][0] = r4[0]; bh[0][1] = r4[1]; bh[1][0] = r4[2]; bh[1][1] = r4[3];
                ldm_x4_t(r4, sbase + (uint32_t)(OFF_KL + (kk + lr) * AT_PITCH + half * 16 + lc) * 2);
                bl[0][0] = r4[0]; bl[0][1] = r4[1]; bl[1][0] = r4[2]; bl[1][1] = r4[3];
#pragma unroll
                for (int t = 0; t < 2; t++) {
                    int nt = half * 2 + t;
                    mma_bf16(s[nt], qfh, bh[t]);
                    mma_bf16(s[nt], qfh, bl[t]);
                    mma_bf16(s[nt], qfl, bh[t]);
                }
            }
        }

#pragma unroll
        for (int nt = 0; nt < 8; nt++)
#pragma unroll
            for (int j = 0; j < 4; j++) s[nt][j] *= SC;

        if (jt == qt) {
#pragma unroll
            for (int nt = 0; nt < 8; nt++) {
                int c0 = nt * 8 + qc;
                if (c0     > row1) s[nt][0] = -1e30f;
                if (c0 + 1 > row1) s[nt][1] = -1e30f;
                if (c0     > row2) s[nt][2] = -1e30f;
                if (c0 + 1 > row2) s[nt][3] = -1e30f;
            }
        }

        float pm1 = -1e30f, pm2 = -1e30f;
#pragma unroll
        for (int nt = 0; nt < 8; nt++) {
            pm1 = fmaxf(pm1, fmaxf(s[nt][0], s[nt][1]));
            pm2 = fmaxf(pm2, fmaxf(s[nt][2], s[nt][3]));
        }
        pm1 = fmaxf(pm1, __shfl_xor_sync(0xffffffff, pm1, 1));
        pm1 = fmaxf(pm1, __shfl_xor_sync(0xffffffff, pm1, 2));
        pm2 = fmaxf(pm2, __shfl_xor_sync(0xffffffff, pm2, 1));
        pm2 = fmaxf(pm2, __shfl_xor_sync(0xffffffff, pm2, 2));

        float mn1 = fmaxf(m1, pm1), mn2 = fmaxf(m2, pm2);
        float rs1 = exp2_fast(m1 - mn1), rs2 = exp2_fast(m2 - mn2);
        m1 = mn1; m2 = mn2;

        float sum1 = 0.0f, sum2 = 0.0f;
        uint32_t phA[8], phB[8], plA[8], plB[8];
#pragma unroll
        for (int nt = 0; nt < 8; nt++) {
            float e0 = exp2_fast(s[nt][0] - m1);
            float e1 = exp2_fast(s[nt][1] - m1);
            float e2 = exp2_fast(s[nt][2] - m2);
            float e3 = exp2_fast(s[nt][3] - m2);
            sum1 += e0 + e1;
            sum2 += e2 + e3;
            __nv_bfloat162 h01 = __floats2bfloat162_rn(e0, e1);
            __nv_bfloat162 h23 = __floats2bfloat162_rn(e2, e3);
            float r0 = e0 - __bfloat162float(h01.x);
            float r1 = e1 - __bfloat162float(h01.y);
            float r2 = e2 - __bfloat162float(h23.x);
            float r3 = e3 - __bfloat162float(h23.y);
            __nv_bfloat162 l01 = __floats2bfloat162_rn(r0, r1);
            __nv_bfloat162 l23 = __floats2bfloat162_rn(r2, r3);
            phA[nt] = *(uint32_t*)&h01;  phB[nt] = *(uint32_t*)&h23;
            plA[nt] = *(uint32_t*)&l01;  plB[nt] = *(uint32_t*)&l23;
        }
        sum1 += __shfl_xor_sync(0xffffffff, sum1, 1);
        sum1 += __shfl_xor_sync(0xffffffff, sum1, 2);
        sum2 += __shfl_xor_sync(0xffffffff, sum2, 1);
        sum2 += __shfl_xor_sync(0xffffffff, sum2, 2);
        l1 = l1 * rs1 + sum1;
        l2 = l2 * rs2 + sum2;

#pragma unroll
        for (int nt = 0; nt < 8; nt++) {
            o[nt][0] *= rs1; o[nt][1] *= rs1;
            o[nt][2] *= rs2; o[nt][3] *= rs2;
        }

#pragma unroll
        for (int t = 0; t < 4; t++) {
            uint32_t aH[4] = {phA[2 * t], phB[2 * t], phA[2 * t + 1], phB[2 * t + 1]};
            uint32_t aL[4] = {plA[2 * t], plB[2 * t], plA[2 * t + 1], plB[2 * t + 1]};
#pragma unroll
            for (int half = 0; half < 4; half++) {
                uint32_t bh[2][2], bl[2][2], r4[4];
                ldm_x4_t(r4, sbase + (uint32_t)(OFF_VH + (t * 16 + lr) * AT_PITCH + half * 16 + lc) * 2);
                bh[0][0] = r4[0]; bh[0][1] = r4[1]; bh[1][0] = r4[2]; bh[1][1] = r4[3];
                ldm_x4_t(r4, sbase + (uint32_t)(OFF_VL + (t * 16 + lr) * AT_PITCH + half * 16 + lc) * 2);
                bl[0][0] = r4[0]; bl[0][1] = r4[1]; bl[1][0] = r4[2]; bl[1][1] = r4[3];
#pragma unroll
                for (int tt = 0; tt < 2; tt++) {
                    int nt = half * 2 + tt;
                    mma_bf16(o[nt], aH, bh[tt]);
                    mma_bf16(o[nt], aL, bh[tt]);
                    mma_bf16(o[nt], aH, bl[tt]);
                }
            }
        }
        __syncthreads();
    }

    float inv1 = 1.0f / l1, inv2 = 1.0f / l2;
    int gr1 = qs0 + row1, gr2 = qs0 + row2;
#pragma unroll
    for (int nt = 0; nt < 8; nt++) {
        int col = h * 64 + nt * 8 + qc;
        float v0 = o[nt][0] * inv1, v1 = o[nt][1] * inv1;
        float v2 = o[nt][2] * inv2, v3 = o[nt][3] * inv2;
        __nv_bfloat162 h01 = __floats2bfloat162_rn(v0, v1);
        __nv_bfloat162 h23 = __floats2bfloat162_rn(v2, v3);
        __nv_bfloat162 l01 = __floats2bfloat162_rn(v0 - __bfloat162float(h01.x),
                                                   v1 - __bfloat162float(h01.y));
        __nv_bfloat162 l23 = __floats2bfloat162_rn(v2 - __bfloat162float(h23.x),
                                                   v3 - __bfloat162float(h23.y));
        *(uint32_t*)&Oh[(size_t)gr1 * H_DIM + col] = *(uint32_t*)&h01;
        *(uint32_t*)&Ol[(size_t)gr1 * H_DIM + col] = *(uint32_t*)&l01;
        *(uint32_t*)&Oh[(size_t)gr2 * H_DIM + col] = *(uint32_t*)&h23;
        *(uint32_t*)&Ol[(size_t)gr2 * H_DIM + col] = *(uint32_t*)&l23;
    }
}

/* ===================================================================== */
extern "C" void kernel_launch(void* const* d_in, const int* in_sizes, int n_in,
                              void* d_out, int out_size) {
    const float* hidden  = (const float*)d_in[0];
    const float* qkv_w   = (const float*)d_in[2];
    const float* dense_w = (const float*)d_in[3];
    float* out = (float*)d_out;

    float* qkv_p;
    cudaGetSymbolAddress((void**)&qkv_p, g_qkv);

    __nv_bfloat16 *xh, *xl, *wqh, *wql, *wdh, *wdl, *ah, *al;
    __nv_bfloat16 *qh2, *ql2, *khT, *klT, *vh2, *vl2;
    cudaGetSymbolAddress((void**)&xh,  g_xh);
    cudaGetSymbolAddress((void**)&xl,  g_xl);
    cudaGetSymbolAddress((void**)&wqh, g_wqh);
    cudaGetSymbolAddress((void**)&wql, g_wql);
    cudaGetSymbolAddress((void**)&wdh, g_wdh);
    cudaGetSymbolAddress((void**)&wdl, g_wdl);
    cudaGetSymbolAddress((void**)&ah,  g_ah);
    cudaGetSymbolAddress((void**)&al,  g_al);
    cudaGetSymbolAddress((void**)&qh2, g_qh2);
    cudaGetSymbolAddress((void**)&ql2, g_ql2);
    cudaGetSymbolAddress((void**)&khT, g_khT);
    cudaGetSymbolAddress((void**)&klT, g_klT);
    cudaGetSymbolAddress((void**)&vh2, g_vh2);
    cudaGetSymbolAddress((void**)&vl2, g_vl2);

    cudaFuncSetAttribute(attn_mma_kernel, cudaFuncAttributeMaxDynamicSharedMemorySize,
                         AT_SMEM_BYTES);
    cudaFuncSetAttribute(gemm_bf16split_v6, cudaFuncAttributeMaxDynamicSharedMemorySize,
                         GEMM_SMEM_BYTES);

    /* 0) split x; split+pad weights */
    {
        int n4 = (S_LEN * H_DIM) / 4;
        split4_kernel<<<(n4 + 255) / 256, 256>>>(hidden, xh, xl, n4);
        int tq = H_DIM * QKV_NP;
        wsplit_pad_kernel<<<(tq + 255) / 256, 256>>>(qkv_w, wqh, wql, QKV_N, QKV_NP, tq);
        int td = H_DIM * HD_NP;
        wsplit_pad_kernel<<<(td + 255) / 256, 256>>>(dense_w, wdh, wdl, H_DIM, HD_NP, td);
    }

    /* 1) qkv = x @ qkv_w (v6) */
    gemm_bf16split_v6<<<dim3(QKV_NP / 128, S_LEN / 128), 128, GEMM_SMEM_BYTES>>>(
        xh, xl, wqh, wql, qkv_p, S_LEN, QKV_N, QKV_NP, H_DIM);

    /* 2) RoPE + bf16 hi/lo split */
    rope_split_bf16_kernel<<<S_LEN, 256>>>(qkv_p, qh2, ql2, khT, klT, vh2, vl2);

    /* 3) flash attention (64-row q tiles, longest-first) */
    attn_mma_kernel<<<dim3(S_LEN / 64, NHEAD), 128, AT_SMEM_BYTES>>>(
        qh2, ql2, khT, klT, vh2, vl2, ah, al);

    /* 4) out = attn @ dense_w (v6) */
    gemm_bf16split_v6<<<dim3(HD_NP / 128, S_LEN / 128), 128, GEMM_SMEM_BYTES>>>(
        ah, al, wdh, wdl, out, S_LEN, H_DIM, HD_NP, H_DIM);
}